// round 3
// baseline (speedup 1.0000x reference)
#include <cuda_runtime.h>

#define BATCH 1024
#define DIM 1024
#define NUM_SAMPLES 100
#define ETA 0.5f
#define KAPPA 0.1f

// One CTA per batch row, 256 threads, occupancy 8 -> all 1024 CTAs resident
// in a single wave (148 SMs x 8 = 1184 slots >= 1024): no wave quantization.
__global__ __launch_bounds__(256, 8) void soliton_kernel(
    const float* __restrict__ residue,
    const float* __restrict__ constraint,
    const float* __restrict__ pert,
    float* __restrict__ out)
{
    const int b   = blockIdx.x;
    const int tid = threadIdx.x;

    // ---- small row loads first: 256 threads, one float4 each ----
    const float4* __restrict__ r4 =
        reinterpret_cast<const float4*>(residue + (size_t)b * DIM);
    const float4* __restrict__ c4 =
        reinterpret_cast<const float4*>(constraint + (size_t)b * DIM);
    float4 rv = r4[tid];
    float4 cv = c4[tid];

    // ---- perturbation sum of squares: 25600 float4 per row, 100 per thread ----
    const float4* __restrict__ p4 =
        reinterpret_cast<const float4*>(pert + (size_t)b * (NUM_SAMPLES * DIM));
    const int N4 = NUM_SAMPLES * DIM / 4;  // 25600

    float s_p = 0.0f;
    #pragma unroll 5
    for (int i = tid; i < N4; i += 256) {
        float4 v = p4[i];
        s_p = fmaf(v.x, v.x, s_p);
        s_p = fmaf(v.y, v.y, s_p);
        s_p = fmaf(v.z, v.z, s_p);
        s_p = fmaf(v.w, v.w, s_p);
    }

    float s_r = rv.x * rv.x + rv.y * rv.y + rv.z * rv.z + rv.w * rv.w;
    float s_c = cv.x * cv.x + cv.y * cv.y + cv.z * cv.z + cv.w * cv.w;

    // ---- 3-way block reduction: warp shuffle then smem across 8 warps ----
    #pragma unroll
    for (int o = 16; o > 0; o >>= 1) {
        s_p += __shfl_down_sync(0xffffffffu, s_p, o);
        s_r += __shfl_down_sync(0xffffffffu, s_r, o);
        s_c += __shfl_down_sync(0xffffffffu, s_c, o);
    }

    __shared__ float sh_p[8], sh_r[8], sh_c[8];
    const int wid  = tid >> 5;
    const int lane = tid & 31;
    if (lane == 0) { sh_p[wid] = s_p; sh_r[wid] = s_r; sh_c[wid] = s_c; }
    __syncthreads();

    if (wid == 0) {
        s_p = (lane < 8) ? sh_p[lane] : 0.0f;
        s_r = (lane < 8) ? sh_r[lane] : 0.0f;
        s_c = (lane < 8) ? sh_c[lane] : 0.0f;
        #pragma unroll
        for (int o = 4; o > 0; o >>= 1) {
            s_p += __shfl_down_sync(0xffffffffu, s_p, o);
            s_r += __shfl_down_sync(0xffffffffu, s_r, o);
            s_c += __shfl_down_sync(0xffffffffu, s_c, o);
        }
        if (lane == 0) {
            float dispersion = s_p * (1.0f / NUM_SAMPLES);
            float energy = s_r;
            float cscale = sqrtf(s_c);
            float energy_density = energy / (cscale + 1e-8f);
            float localization = (energy > 0.0f)
                                   ? ETA / (energy_density + 1e-8f)
                                   : cscale;
            float ratio = dispersion / (localization + 1e-8f);
            // Output tuple order: is_soliton, dispersion, localization, ratio
            out[b]             = (ratio < KAPPA) ? 1.0f : 0.0f;
            out[BATCH + b]     = dispersion;
            out[2 * BATCH + b] = localization;
            out[3 * BATCH + b] = ratio;
        }
    }
}

extern "C" void kernel_launch(void* const* d_in, const int* in_sizes, int n_in,
                              void* d_out, int out_size) {
    const float* residue    = (const float*)d_in[0];
    const float* constraint = (const float*)d_in[1];
    const float* pert       = (const float*)d_in[2];

    // Robustness: identify the perturbation tensor by size in case of ordering drift.
    for (int i = 0; i < n_in; i++) {
        if (in_sizes[i] == BATCH * NUM_SAMPLES * DIM) {
            pert = (const float*)d_in[i];
        }
    }
    if (pert == (const float*)d_in[0]) {
        residue    = (const float*)d_in[1];
        constraint = (const float*)d_in[2];
    } else if (pert == (const float*)d_in[1]) {
        residue    = (const float*)d_in[0];
        constraint = (const float*)d_in[2];
    }

    float* out = (float*)d_out;
    soliton_kernel<<<BATCH, 256>>>(residue, constraint, pert, out);
}

// round 4
// speedup vs baseline: 1.0365x; 1.0365x over previous
#include <cuda_runtime.h>

#define BATCH 1024
#define DIM 1024
#define NUM_SAMPLES 100
#define ETA 0.5f
#define KAPPA 0.1f

// R1 shape (512 threads, occ 4, single accumulator, unroll 5) + __ldcs
// streaming policy on the once-read perturbation tensor.
__global__ __launch_bounds__(512, 4) void soliton_kernel(
    const float* __restrict__ residue,
    const float* __restrict__ constraint,
    const float* __restrict__ pert,
    float* __restrict__ out)
{
    const int b   = blockIdx.x;
    const int tid = threadIdx.x;

    // ---- perturbation sum of squares: 102400 floats = 25600 float4 ----
    const float4* __restrict__ p4 =
        reinterpret_cast<const float4*>(pert + (size_t)b * (NUM_SAMPLES * DIM));
    const int N4 = NUM_SAMPLES * DIM / 4;  // 25600

    float s_p = 0.0f;
    #pragma unroll 5
    for (int i = tid; i < N4; i += 512) {
        float4 v = __ldcs(&p4[i]);   // evict-first: data is read exactly once
        s_p = fmaf(v.x, v.x, s_p);
        s_p = fmaf(v.y, v.y, s_p);
        s_p = fmaf(v.z, v.z, s_p);
        s_p = fmaf(v.w, v.w, s_p);
    }

    // ---- residue energy + constraint norm^2: 1024 floats = 256 float4 each ----
    const float4* __restrict__ r4 =
        reinterpret_cast<const float4*>(residue + (size_t)b * DIM);
    const float4* __restrict__ c4 =
        reinterpret_cast<const float4*>(constraint + (size_t)b * DIM);

    float s_r = 0.0f, s_c = 0.0f;
    if (tid < DIM / 4) {  // 256 threads, one float4 each
        float4 v = __ldcs(&r4[tid]);
        s_r = v.x * v.x + v.y * v.y + v.z * v.z + v.w * v.w;
        float4 w = __ldcs(&c4[tid]);
        s_c = w.x * w.x + w.y * w.y + w.z * w.z + w.w * w.w;
    }

    // ---- 3-way block reduction: warp shuffle then smem across 16 warps ----
    #pragma unroll
    for (int o = 16; o > 0; o >>= 1) {
        s_p += __shfl_down_sync(0xffffffffu, s_p, o);
        s_r += __shfl_down_sync(0xffffffffu, s_r, o);
        s_c += __shfl_down_sync(0xffffffffu, s_c, o);
    }

    __shared__ float sh_p[16], sh_r[16], sh_c[16];
    const int wid  = tid >> 5;
    const int lane = tid & 31;
    if (lane == 0) { sh_p[wid] = s_p; sh_r[wid] = s_r; sh_c[wid] = s_c; }
    __syncthreads();

    if (wid == 0) {
        s_p = (lane < 16) ? sh_p[lane] : 0.0f;
        s_r = (lane < 16) ? sh_r[lane] : 0.0f;
        s_c = (lane < 16) ? sh_c[lane] : 0.0f;
        #pragma unroll
        for (int o = 8; o > 0; o >>= 1) {
            s_p += __shfl_down_sync(0xffffffffu, s_p, o);
            s_r += __shfl_down_sync(0xffffffffu, s_r, o);
            s_c += __shfl_down_sync(0xffffffffu, s_c, o);
        }
        if (lane == 0) {
            float dispersion = s_p * (1.0f / NUM_SAMPLES);
            float energy = s_r;
            float cscale = sqrtf(s_c);
            float energy_density = energy / (cscale + 1e-8f);
            float localization = (energy > 0.0f)
                                   ? ETA / (energy_density + 1e-8f)
                                   : cscale;
            float ratio = dispersion / (localization + 1e-8f);
            // Output tuple order: is_soliton, dispersion, localization, ratio
            out[b]             = (ratio < KAPPA) ? 1.0f : 0.0f;
            out[BATCH + b]     = dispersion;
            out[2 * BATCH + b] = localization;
            out[3 * BATCH + b] = ratio;
        }
    }
}

extern "C" void kernel_launch(void* const* d_in, const int* in_sizes, int n_in,
                              void* d_out, int out_size) {
    const float* residue    = (const float*)d_in[0];
    const float* constraint = (const float*)d_in[1];
    const float* pert       = (const float*)d_in[2];

    // Robustness: identify the perturbation tensor by size in case of ordering drift.
    for (int i = 0; i < n_in; i++) {
        if (in_sizes[i] == BATCH * NUM_SAMPLES * DIM) {
            pert = (const float*)d_in[i];
        }
    }
    if (pert == (const float*)d_in[0]) {
        residue    = (const float*)d_in[1];
        constraint = (const float*)d_in[2];
    } else if (pert == (const float*)d_in[1]) {
        residue    = (const float*)d_in[0];
        constraint = (const float*)d_in[2];
    }

    float* out = (float*)d_out;
    soliton_kernel<<<BATCH, 512>>>(residue, constraint, pert, out);
}